// round 15
// baseline (speedup 1.0000x reference)
#include <cuda_runtime.h>
#include <cuda_fp16.h>
#include <cstdint>

#define NN 100000
#define DIM 256
#define NE 500000
#define MTILES 782            // ceil(NN/128)
#define CAP 64                // bucket capacity per (rel, node); fallback if exceeded

// ---------------------------------------------------------------------------
// __device__ global scratch (allocation-free rule)
// ---------------------------------------------------------------------------
__device__ __half g_msg1[(size_t)NN * DIM];     // fp16 messages
__device__ __half g_msg2[(size_t)NN * DIM];
__device__ __half g_xh[(size_t)NN * DIM];
__device__ __half g_wh[3 * DIM * DIM];          // [rel][n][k], 1.1 folded into rel 0
__device__ int g_cnt[2 * NN];
__device__ int g_bkt[(size_t)2 * NN * CAP];

// ---------------------------------------------------------------------------
// PTX helpers (baseline ISA only — harness targets compute_103, no 'a' features)
// ---------------------------------------------------------------------------
__device__ __forceinline__ uint32_t smem_u32(const void* p) {
    uint32_t a;
    asm("{ .reg .u64 t; cvta.to.shared.u64 t, %1; cvt.u32.u64 %0, t; }"
        : "=r"(a) : "l"(p));
    return a;
}

#define CP_ASYNC16(dst, src) \
    asm volatile("cp.async.cg.shared.global [%0], [%1], 16;" :: "r"(dst), "l"(src))
#define CP_COMMIT() asm volatile("cp.async.commit_group;" ::: "memory")
#define CP_WAIT(n)  asm volatile("cp.async.wait_group %0;" :: "n"(n) : "memory")

#define LDSM_X4(r, addr) \
    asm volatile("ldmatrix.sync.aligned.m8n8.x4.shared.b16 {%0,%1,%2,%3}, [%4];" \
        : "=r"((r)[0]), "=r"((r)[1]), "=r"((r)[2]), "=r"((r)[3]) : "r"(addr))

#define MMA16816(d, a, b0, b1) \
    asm volatile("mma.sync.aligned.m16n8k16.row.col.f32.f16.f16.f32 " \
        "{%0,%1,%2,%3}, {%4,%5,%6,%7}, {%8,%9}, {%0,%1,%2,%3};" \
        : "+f"((d)[0]), "+f"((d)[1]), "+f"((d)[2]), "+f"((d)[3]) \
        : "r"((a)[0]), "r"((a)[1]), "r"((a)[2]), "r"((a)[3]), "r"(b0), "r"(b1))

__device__ __forceinline__ void red_add_v4(float4* p, float4 v) {
    asm volatile("red.global.add.v4.f32 [%0], {%1,%2,%3,%4};"
                 :: "l"(p), "f"(v.x), "f"(v.y), "f"(v.z), "f"(v.w)
                 : "memory");
}

// ---------------------------------------------------------------------------
// Prep: convert x to fp16
// ---------------------------------------------------------------------------
__global__ __launch_bounds__(256) void conv_x(const float* __restrict__ x) {
    size_t i = (size_t)blockIdx.x * 256 + threadIdx.x;   // per float4
    if (i >= (size_t)NN * DIM / 4) return;
    float4 v = reinterpret_cast<const float4*>(x)[i];
    __half2 h01 = __floats2half2_rn(v.x, v.y);
    __half2 h23 = __floats2half2_rn(v.z, v.w);
    reinterpret_cast<__half2*>(g_xh)[2 * i]     = h01;
    reinterpret_cast<__half2*>(g_xh)[2 * i + 1] = h23;
}

// Prep: transpose + convert W  (g_wh[rel*65536 + n*256 + k] = fp16(Weff[k][n]))
__global__ __launch_bounds__(256) void conv_w(
    const float* __restrict__ Ws, const float* __restrict__ W1,
    const float* __restrict__ W2)
{
    int idx = blockIdx.x * 256 + threadIdx.x;            // 0 .. 196607
    if (idx >= 3 * DIM * DIM) return;
    int rel = idx >> 16;
    int r   = idx & 65535;
    int n   = r >> 8;
    int k   = r & 255;
    const float* W = (rel == 0) ? Ws : (rel == 1) ? W1 : W2;
    float v = W[k * DIM + n] * ((rel == 0) ? 1.1f : 1.0f);
    g_wh[idx] = __float2half_rn(v);
}

// ---------------------------------------------------------------------------
// HMMA GEMM (R11-proven form): 128x128 tile/CTA, K = 256, cp.async both
// operands, fp16 in / fp32 accum. grid (6, 782): adjacent bids share A in L2.
// rel 0 writes fp32 to h; rel 1/2 write fp16 to g_msg1/g_msg2.
// ---------------------------------------------------------------------------
#define CHUNK_BYTES (128 * 128)
#define BUF_BYTES   (2 * CHUNK_BYTES)
#define GEMM_SMEM   (2 * BUF_BYTES)

__global__ __launch_bounds__(256) void gemm_mma(float* __restrict__ h)
{
    extern __shared__ __align__(128) char smem[];
    const int tid    = threadIdx.x;
    const int wid    = tid >> 5, lane = tid & 31;
    const int warp_m = wid & 3;
    const int warp_n = wid >> 2;
    const int ntile  = blockIdx.x, mtile = blockIdx.y;
    const int rel    = ntile >> 1, n0 = (ntile & 1) << 7;
    const int row0   = mtile * 128;

    uint32_t sbase = smem_u32(smem);

    const char* Asrc = (const char*)g_xh;
    const char* Bsrc = (const char*)g_wh + (size_t)rel * 131072;

    float acc[2][8][4];
#pragma unroll
    for (int mt = 0; mt < 2; mt++)
#pragma unroll
        for (int nt = 0; nt < 8; nt++)
#pragma unroll
            for (int q = 0; q < 4; q++) acc[mt][nt][q] = 0.f;

    auto load_chunk = [&](int kc, int bsel) {
        uint32_t bb = sbase + bsel * BUF_BYTES;
#pragma unroll
        for (int q = 0; q < 8; q++) {
            int s    = tid + (q << 8);          // 0..2047 16B segments
            int part = s >> 10;                 // 0:A 1:B
            int s10  = s & 1023;
            int row  = s10 >> 3;
            int j    = s10 & 7;
            uint32_t dst = bb + part * CHUNK_BYTES + row * 128 + ((j ^ (row & 7)) << 4);
            const char* src;
            if (part == 0) {
                int gr = row0 + row; if (gr >= NN) gr = NN - 1;
                src = Asrc + (size_t)gr * 512 + kc * 128 + j * 16;
            } else {
                src = Bsrc + (size_t)(n0 + row) * 512 + kc * 128 + j * 16;
            }
            CP_ASYNC16(dst, src);
        }
        CP_COMMIT();
    };

    load_chunk(0, 0);

    for (int c = 0; c < 4; c++) {
        int b = c & 1;
        if (c + 1 < 4) { load_chunk(c + 1, 1 - b); CP_WAIT(1); }
        else           { CP_WAIT(0); }
        __syncthreads();

        uint32_t Ab = sbase + b * BUF_BYTES;
        uint32_t Bb = Ab + CHUNK_BYTES;

#pragma unroll
        for (int ks = 0; ks < 4; ks++) {
            uint32_t a[2][4];
#pragma unroll
            for (int mt = 0; mt < 2; mt++) {
                int r = warp_m * 32 + mt * 16 + (lane & 15);
                int j = ks * 2 + (lane >> 4);
                LDSM_X4(a[mt], Ab + r * 128 + ((j ^ (r & 7)) << 4));
            }
            uint32_t bf[4][4];
#pragma unroll
            for (int nt2 = 0; nt2 < 4; nt2++) {
                int g = lane >> 3;
                int n = warp_n * 64 + nt2 * 16 + ((g >> 1) << 3) + (lane & 7);
                int j = ks * 2 + (g & 1);
                LDSM_X4(bf[nt2], Bb + n * 128 + ((j ^ (n & 7)) << 4));
            }
#pragma unroll
            for (int mt = 0; mt < 2; mt++)
#pragma unroll
                for (int nt2 = 0; nt2 < 4; nt2++) {
                    MMA16816(acc[mt][nt2 * 2],     a[mt], bf[nt2][0], bf[nt2][1]);
                    MMA16816(acc[mt][nt2 * 2 + 1], a[mt], bf[nt2][2], bf[nt2][3]);
                }
        }
        __syncthreads();
    }

    if (rel == 0) {
#pragma unroll
        for (int mt = 0; mt < 2; mt++) {
            int r = row0 + warp_m * 32 + mt * 16 + (lane >> 2);
#pragma unroll
            for (int nt = 0; nt < 8; nt++) {
                int colb = n0 + warp_n * 64 + nt * 8 + 2 * (lane & 3);
                if (r < NN)
                    *reinterpret_cast<float2*>(h + (size_t)r * DIM + colb) =
                        make_float2(acc[mt][nt][0], acc[mt][nt][1]);
                if (r + 8 < NN)
                    *reinterpret_cast<float2*>(h + (size_t)(r + 8) * DIM + colb) =
                        make_float2(acc[mt][nt][2], acc[mt][nt][3]);
            }
        }
    } else {
        __half* mp = (rel == 1) ? g_msg1 : g_msg2;
#pragma unroll
        for (int mt = 0; mt < 2; mt++) {
            int r = row0 + warp_m * 32 + mt * 16 + (lane >> 2);
#pragma unroll
            for (int nt = 0; nt < 8; nt++) {
                int colb = n0 + warp_n * 64 + nt * 8 + 2 * (lane & 3);
                if (r < NN)
                    *reinterpret_cast<__half2*>(mp + (size_t)r * DIM + colb) =
                        __floats2half2_rn(acc[mt][nt][0], acc[mt][nt][1]);
                if (r + 8 < NN)
                    *reinterpret_cast<__half2*>(mp + (size_t)(r + 8) * DIM + colb) =
                        __floats2half2_rn(acc[mt][nt][2], acc[mt][nt][3]);
            }
        }
    }
}

// ---------------------------------------------------------------------------
// Destination buckets (side stream: independent of GEMM chain)
// ---------------------------------------------------------------------------
__global__ __launch_bounds__(256) void zero_cnt() {
    int i = blockIdx.x * 256 + threadIdx.x;
    if (i < 2 * NN) g_cnt[i] = 0;
}

__global__ __launch_bounds__(256) void bucket_fill(
    const int* __restrict__ src1, const int* __restrict__ dst1,
    const int* __restrict__ src2, const int* __restrict__ dst2,
    float* __restrict__ h)
{
    int e = blockIdx.x * 256 + threadIdx.x;
    if (e >= NE) return;
    int rel = blockIdx.y;
    const int* src = rel ? src2 : src1;
    const int* dst = rel ? dst2 : dst1;
    int s = __ldg(src + e);
    int d = __ldg(dst + e);
    int slot = atomicAdd(&g_cnt[rel * NN + d], 1);
    if (slot < CAP) {
        g_bkt[((size_t)(rel * NN + d)) * CAP + slot] = s;
    } else {
        // overflow fallback (statistically never with CAP=64): atomic into h
        const __half2* sp = reinterpret_cast<const __half2*>(
            (rel ? g_msg2 : g_msg1) + (size_t)s * DIM);
        float4* dp = reinterpret_cast<float4*>(h + (size_t)d * DIM);
        for (int i = 0; i < DIM / 4; i++) {
            float2 p0 = __half22float2(sp[2 * i]);
            float2 p1 = __half22float2(sp[2 * i + 1]);
            red_add_v4(dp + i, make_float4(p0.x, p0.y, p1.x, p1.y));
        }
    }
}

// ---------------------------------------------------------------------------
// Gather + finalize: warp per (node, column-half). 200k warps for 2x the
// independent load streams vs warp-per-node. Lane owns 4 cols (uint2 = 8B
// per edge row). acc = h_self + sum fp16 msg; relu(acc + bias) -> h.
// ---------------------------------------------------------------------------
__global__ __launch_bounds__(256) void gather_finalize(
    float* __restrict__ h, const float* __restrict__ bias)
{
    int gw   = (blockIdx.x * 256 + threadIdx.x) >> 5;   // 0 .. 2*NN-1
    int lane = threadIdx.x & 31;
    if (gw >= 2 * NN) return;
    int w  = gw >> 1;            // node
    int hf = gw & 1;             // column half (0: cols 0-127, 1: cols 128-255)

    float4* hp = reinterpret_cast<float4*>(h + (size_t)w * DIM + hf * 128) + lane;
    float4 a = *hp;

#pragma unroll
    for (int rel = 0; rel < 2; rel++) {
        int n = g_cnt[rel * NN + w];
        if (n > CAP) n = CAP;
        const uint2* msg = reinterpret_cast<const uint2*>(rel ? g_msg2 : g_msg1);
        const int* bkt = g_bkt + ((size_t)(rel * NN + w)) * CAP;
        int myidx = (lane < n) ? __ldg(bkt + lane) : 0;
        int n1 = n < 32 ? n : 32;
        for (int i = 0; i < n1; i++) {
            int s = __shfl_sync(0xFFFFFFFFu, myidx, i);
            uint2 v = msg[(size_t)s * 64 + hf * 32 + lane];   // 4 halves
            float2 p0 = __half22float2(*reinterpret_cast<const __half2*>(&v.x));
            float2 p1 = __half22float2(*reinterpret_cast<const __half2*>(&v.y));
            a.x += p0.x; a.y += p0.y; a.z += p1.x; a.w += p1.y;
        }
        for (int i = 32; i < n; i++) {                        // rare tail
            int s = __ldg(bkt + i);
            uint2 v = msg[(size_t)s * 64 + hf * 32 + lane];
            float2 p0 = __half22float2(*reinterpret_cast<const __half2*>(&v.x));
            float2 p1 = __half22float2(*reinterpret_cast<const __half2*>(&v.y));
            a.x += p0.x; a.y += p0.y; a.z += p1.x; a.w += p1.y;
        }
    }

    float4 b = __ldg(reinterpret_cast<const float4*>(bias + hf * 128) + lane);
    a.x = fmaxf(a.x + b.x, 0.f);
    a.y = fmaxf(a.y + b.y, 0.f);
    a.z = fmaxf(a.z + b.z, 0.f);
    a.w = fmaxf(a.w + b.w, 0.f);
    *hp = a;
}

// ---------------------------------------------------------------------------
// Launch DAG:
//   side:  conv_w -> (e_w) -> zero_cnt -> bucket_fill -> (e_join)
//   main:  conv_x -> wait(e_w) -> gemm -> wait(e_join) -> gather_finalize
// ---------------------------------------------------------------------------
extern "C" void kernel_launch(void* const* d_in, const int* in_sizes, int n_in,
                              void* d_out, int out_size)
{
    const float* x    = (const float*)d_in[0];
    const float* Ws   = (const float*)d_in[1];
    const float* W1   = (const float*)d_in[2];
    const float* W2   = (const float*)d_in[3];
    const float* bias = (const float*)d_in[4];
    const int* src1   = (const int*)d_in[5];
    const int* dst1   = (const int*)d_in[6];
    const int* src2   = (const int*)d_in[7];
    const int* dst2   = (const int*)d_in[8];
    float* h = (float*)d_out;

    cudaFuncSetAttribute(gemm_mma, cudaFuncAttributeMaxDynamicSharedMemorySize, GEMM_SMEM);

    cudaStream_t s2;
    cudaEvent_t e_fork, e_w, e_join;
    cudaStreamCreateWithFlags(&s2, cudaStreamNonBlocking);
    cudaEventCreateWithFlags(&e_fork, cudaEventDisableTiming);
    cudaEventCreateWithFlags(&e_w,    cudaEventDisableTiming);
    cudaEventCreateWithFlags(&e_join, cudaEventDisableTiming);

    // fork
    cudaEventRecord(e_fork, 0);
    cudaStreamWaitEvent(s2, e_fork, 0);

    // side stream: W conversion, then buckets
    conv_w<<<(3 * DIM * DIM + 255) / 256, 256, 0, s2>>>(Ws, W1, W2);
    cudaEventRecord(e_w, s2);
    zero_cnt<<<(2 * NN + 255) / 256, 256, 0, s2>>>();
    dim3 fgrid((NE + 255) / 256, 2);
    bucket_fill<<<fgrid, 256, 0, s2>>>(src1, dst1, src2, dst2, h);
    cudaEventRecord(e_join, s2);

    // main stream: x conversion, gemm (after W ready)
    int nx = (int)(((size_t)NN * DIM / 4 + 255) / 256);
    conv_x<<<nx, 256>>>(x);
    cudaStreamWaitEvent(0, e_w, 0);
    dim3 ggrid(6, MTILES);
    gemm_mma<<<ggrid, 256, GEMM_SMEM>>>(h);

    // join, then finalize
    cudaStreamWaitEvent(0, e_join, 0);
    gather_finalize<<<(2 * NN * 32 + 255) / 256, 256>>>(h, bias);
}

// round 16
// speedup vs baseline: 1.0736x; 1.0736x over previous
#include <cuda_runtime.h>
#include <cuda_fp16.h>
#include <cstdint>

#define NN 100000
#define DIM 256
#define NE 500000
#define MTILES 782            // ceil(NN/128)
#define CAP 64                // bucket capacity per (rel, node); fallback if exceeded

// ---------------------------------------------------------------------------
// __device__ global scratch (allocation-free rule)
// ---------------------------------------------------------------------------
__device__ __half g_msg1[(size_t)NN * DIM];     // fp16 messages
__device__ __half g_msg2[(size_t)NN * DIM];
__device__ __half g_xh[(size_t)NN * DIM];
__device__ __half g_wh[3 * DIM * DIM];          // [rel][n][k], 1.1 folded into rel 0
__device__ int g_cnt[2 * NN];
__device__ int g_bkt[(size_t)2 * NN * CAP];

// ---------------------------------------------------------------------------
// PTX helpers (baseline ISA only — harness targets compute_103, no 'a' features)
// ---------------------------------------------------------------------------
__device__ __forceinline__ uint32_t smem_u32(const void* p) {
    uint32_t a;
    asm("{ .reg .u64 t; cvta.to.shared.u64 t, %1; cvt.u32.u64 %0, t; }"
        : "=r"(a) : "l"(p));
    return a;
}

#define CP_ASYNC16(dst, src) \
    asm volatile("cp.async.cg.shared.global [%0], [%1], 16;" :: "r"(dst), "l"(src))
#define CP_COMMIT() asm volatile("cp.async.commit_group;" ::: "memory")
#define CP_WAIT(n)  asm volatile("cp.async.wait_group %0;" :: "n"(n) : "memory")

#define LDSM_X4(r, addr) \
    asm volatile("ldmatrix.sync.aligned.m8n8.x4.shared.b16 {%0,%1,%2,%3}, [%4];" \
        : "=r"((r)[0]), "=r"((r)[1]), "=r"((r)[2]), "=r"((r)[3]) : "r"(addr))

#define MMA16816(d, a, b0, b1) \
    asm volatile("mma.sync.aligned.m16n8k16.row.col.f32.f16.f16.f32 " \
        "{%0,%1,%2,%3}, {%4,%5,%6,%7}, {%8,%9}, {%0,%1,%2,%3};" \
        : "+f"((d)[0]), "+f"((d)[1]), "+f"((d)[2]), "+f"((d)[3]) \
        : "r"((a)[0]), "r"((a)[1]), "r"((a)[2]), "r"((a)[3]), "r"(b0), "r"(b1))

__device__ __forceinline__ void red_add_v4(float4* p, float4 v) {
    asm volatile("red.global.add.v4.f32 [%0], {%1,%2,%3,%4};"
                 :: "l"(p), "f"(v.x), "f"(v.y), "f"(v.z), "f"(v.w)
                 : "memory");
}

// ---------------------------------------------------------------------------
// Prep: convert x to fp16
// ---------------------------------------------------------------------------
__global__ __launch_bounds__(256) void conv_x(const float* __restrict__ x) {
    size_t i = (size_t)blockIdx.x * 256 + threadIdx.x;   // per float4
    if (i >= (size_t)NN * DIM / 4) return;
    float4 v = reinterpret_cast<const float4*>(x)[i];
    __half2 h01 = __floats2half2_rn(v.x, v.y);
    __half2 h23 = __floats2half2_rn(v.z, v.w);
    reinterpret_cast<__half2*>(g_xh)[2 * i]     = h01;
    reinterpret_cast<__half2*>(g_xh)[2 * i + 1] = h23;
}

// Prep: transpose + convert W  (g_wh[rel*65536 + n*256 + k] = fp16(Weff[k][n]))
__global__ __launch_bounds__(256) void conv_w(
    const float* __restrict__ Ws, const float* __restrict__ W1,
    const float* __restrict__ W2)
{
    int idx = blockIdx.x * 256 + threadIdx.x;            // 0 .. 196607
    if (idx >= 3 * DIM * DIM) return;
    int rel = idx >> 16;
    int r   = idx & 65535;
    int n   = r >> 8;
    int k   = r & 255;
    const float* W = (rel == 0) ? Ws : (rel == 1) ? W1 : W2;
    float v = W[k * DIM + n] * ((rel == 0) ? 1.1f : 1.0f);
    g_wh[idx] = __float2half_rn(v);
}

// ---------------------------------------------------------------------------
// HMMA GEMM (R11-proven form + 2 CTAs/SM): 128x128 tile/CTA, K = 256,
// cp.async both operands, fp16 in / fp32 accum. grid (6, 782).
// __launch_bounds__(256, 2) caps regs at 128 so two CTAs co-reside and
// fill each other's barrier bubbles.
// ---------------------------------------------------------------------------
#define CHUNK_BYTES (128 * 128)
#define BUF_BYTES   (2 * CHUNK_BYTES)
#define GEMM_SMEM   (2 * BUF_BYTES)

__global__ __launch_bounds__(256, 2) void gemm_mma(float* __restrict__ h)
{
    extern __shared__ __align__(128) char smem[];
    const int tid    = threadIdx.x;
    const int wid    = tid >> 5, lane = tid & 31;
    const int warp_m = wid & 3;
    const int warp_n = wid >> 2;
    const int ntile  = blockIdx.x, mtile = blockIdx.y;
    const int rel    = ntile >> 1, n0 = (ntile & 1) << 7;
    const int row0   = mtile * 128;

    uint32_t sbase = smem_u32(smem);

    const char* Asrc = (const char*)g_xh;
    const char* Bsrc = (const char*)g_wh + (size_t)rel * 131072;

    float acc[2][8][4];
#pragma unroll
    for (int mt = 0; mt < 2; mt++)
#pragma unroll
        for (int nt = 0; nt < 8; nt++)
#pragma unroll
            for (int q = 0; q < 4; q++) acc[mt][nt][q] = 0.f;

    auto load_chunk = [&](int kc, int bsel) {
        uint32_t bb = sbase + bsel * BUF_BYTES;
#pragma unroll
        for (int q = 0; q < 8; q++) {
            int s    = tid + (q << 8);          // 0..2047 16B segments
            int part = s >> 10;                 // 0:A 1:B
            int s10  = s & 1023;
            int row  = s10 >> 3;
            int j    = s10 & 7;
            uint32_t dst = bb + part * CHUNK_BYTES + row * 128 + ((j ^ (row & 7)) << 4);
            const char* src;
            if (part == 0) {
                int gr = row0 + row; if (gr >= NN) gr = NN - 1;
                src = Asrc + (size_t)gr * 512 + kc * 128 + j * 16;
            } else {
                src = Bsrc + (size_t)(n0 + row) * 512 + kc * 128 + j * 16;
            }
            CP_ASYNC16(dst, src);
        }
        CP_COMMIT();
    };

    load_chunk(0, 0);

    for (int c = 0; c < 4; c++) {
        int b = c & 1;
        if (c + 1 < 4) { load_chunk(c + 1, 1 - b); CP_WAIT(1); }
        else           { CP_WAIT(0); }
        __syncthreads();

        uint32_t Ab = sbase + b * BUF_BYTES;
        uint32_t Bb = Ab + CHUNK_BYTES;

#pragma unroll
        for (int ks = 0; ks < 4; ks++) {
            uint32_t a[2][4];
#pragma unroll
            for (int mt = 0; mt < 2; mt++) {
                int r = warp_m * 32 + mt * 16 + (lane & 15);
                int j = ks * 2 + (lane >> 4);
                LDSM_X4(a[mt], Ab + r * 128 + ((j ^ (r & 7)) << 4));
            }
            uint32_t bf[4][4];
#pragma unroll
            for (int nt2 = 0; nt2 < 4; nt2++) {
                int g = lane >> 3;
                int n = warp_n * 64 + nt2 * 16 + ((g >> 1) << 3) + (lane & 7);
                int j = ks * 2 + (g & 1);
                LDSM_X4(bf[nt2], Bb + n * 128 + ((j ^ (n & 7)) << 4));
            }
#pragma unroll
            for (int mt = 0; mt < 2; mt++)
#pragma unroll
                for (int nt2 = 0; nt2 < 4; nt2++) {
                    MMA16816(acc[mt][nt2 * 2],     a[mt], bf[nt2][0], bf[nt2][1]);
                    MMA16816(acc[mt][nt2 * 2 + 1], a[mt], bf[nt2][2], bf[nt2][3]);
                }
        }
        __syncthreads();
    }

    if (rel == 0) {
#pragma unroll
        for (int mt = 0; mt < 2; mt++) {
            int r = row0 + warp_m * 32 + mt * 16 + (lane >> 2);
#pragma unroll
            for (int nt = 0; nt < 8; nt++) {
                int colb = n0 + warp_n * 64 + nt * 8 + 2 * (lane & 3);
                if (r < NN)
                    *reinterpret_cast<float2*>(h + (size_t)r * DIM + colb) =
                        make_float2(acc[mt][nt][0], acc[mt][nt][1]);
                if (r + 8 < NN)
                    *reinterpret_cast<float2*>(h + (size_t)(r + 8) * DIM + colb) =
                        make_float2(acc[mt][nt][2], acc[mt][nt][3]);
            }
        }
    } else {
        __half* mp = (rel == 1) ? g_msg1 : g_msg2;
#pragma unroll
        for (int mt = 0; mt < 2; mt++) {
            int r = row0 + warp_m * 32 + mt * 16 + (lane >> 2);
#pragma unroll
            for (int nt = 0; nt < 8; nt++) {
                int colb = n0 + warp_n * 64 + nt * 8 + 2 * (lane & 3);
                if (r < NN)
                    *reinterpret_cast<__half2*>(mp + (size_t)r * DIM + colb) =
                        __floats2half2_rn(acc[mt][nt][0], acc[mt][nt][1]);
                if (r + 8 < NN)
                    *reinterpret_cast<__half2*>(mp + (size_t)(r + 8) * DIM + colb) =
                        __floats2half2_rn(acc[mt][nt][2], acc[mt][nt][3]);
            }
        }
    }
}

// ---------------------------------------------------------------------------
// Destination buckets (side stream: independent of GEMM chain)
// ---------------------------------------------------------------------------
__global__ __launch_bounds__(256) void zero_cnt() {
    int i = blockIdx.x * 256 + threadIdx.x;
    if (i < 2 * NN) g_cnt[i] = 0;
}

__global__ __launch_bounds__(256) void bucket_fill(
    const int* __restrict__ src1, const int* __restrict__ dst1,
    const int* __restrict__ src2, const int* __restrict__ dst2,
    float* __restrict__ h)
{
    int e = blockIdx.x * 256 + threadIdx.x;
    if (e >= NE) return;
    int rel = blockIdx.y;
    const int* src = rel ? src2 : src1;
    const int* dst = rel ? dst2 : dst1;
    int s = __ldg(src + e);
    int d = __ldg(dst + e);
    int slot = atomicAdd(&g_cnt[rel * NN + d], 1);
    if (slot < CAP) {
        g_bkt[((size_t)(rel * NN + d)) * CAP + slot] = s;
    } else {
        // overflow fallback (statistically never with CAP=64): atomic into h
        const __half2* sp = reinterpret_cast<const __half2*>(
            (rel ? g_msg2 : g_msg1) + (size_t)s * DIM);
        float4* dp = reinterpret_cast<float4*>(h + (size_t)d * DIM);
        for (int i = 0; i < DIM / 4; i++) {
            float2 p0 = __half22float2(sp[2 * i]);
            float2 p1 = __half22float2(sp[2 * i + 1]);
            red_add_v4(dp + i, make_float4(p0.x, p0.y, p1.x, p1.y));
        }
    }
}

// ---------------------------------------------------------------------------
// Gather + finalize (R11-proven form): warp per node; lane owns cols [8L,8L+8).
// acc = h_self[v] + sum fp16 msg rows; relu(acc + bias) -> h[v].
// ---------------------------------------------------------------------------
__global__ __launch_bounds__(256) void gather_finalize(
    float* __restrict__ h, const float* __restrict__ bias)
{
    int w    = (blockIdx.x * 256 + threadIdx.x) >> 5;
    int lane = threadIdx.x & 31;
    if (w >= NN) return;

    float4* h4 = reinterpret_cast<float4*>(h) + (size_t)w * 64;
    float4 a0 = h4[2 * lane];
    float4 a1 = h4[2 * lane + 1];

#pragma unroll
    for (int rel = 0; rel < 2; rel++) {
        int n = g_cnt[rel * NN + w];
        if (n > CAP) n = CAP;
        const uint4* msg = reinterpret_cast<const uint4*>(rel ? g_msg2 : g_msg1);
        const int* bkt = g_bkt + ((size_t)(rel * NN + w)) * CAP;
        int myidx = (lane < n) ? __ldg(bkt + lane) : 0;
        int n1 = n < 32 ? n : 32;
        for (int i = 0; i < n1; i++) {
            int s = __shfl_sync(0xFFFFFFFFu, myidx, i);
            uint4 v = msg[(size_t)s * 32 + lane];       // 8 halves = cols 8L..8L+7
            float2 p0 = __half22float2(*reinterpret_cast<const __half2*>(&v.x));
            float2 p1 = __half22float2(*reinterpret_cast<const __half2*>(&v.y));
            float2 p2 = __half22float2(*reinterpret_cast<const __half2*>(&v.z));
            float2 p3 = __half22float2(*reinterpret_cast<const __half2*>(&v.w));
            a0.x += p0.x; a0.y += p0.y; a0.z += p1.x; a0.w += p1.y;
            a1.x += p2.x; a1.y += p2.y; a1.z += p3.x; a1.w += p3.y;
        }
        for (int i = 32; i < n; i++) {                  // rare tail (deg > 32)
            int s = __ldg(bkt + i);
            uint4 v = msg[(size_t)s * 32 + lane];
            float2 p0 = __half22float2(*reinterpret_cast<const __half2*>(&v.x));
            float2 p1 = __half22float2(*reinterpret_cast<const __half2*>(&v.y));
            float2 p2 = __half22float2(*reinterpret_cast<const __half2*>(&v.z));
            float2 p3 = __half22float2(*reinterpret_cast<const __half2*>(&v.w));
            a0.x += p0.x; a0.y += p0.y; a0.z += p1.x; a0.w += p1.y;
            a1.x += p2.x; a1.y += p2.y; a1.z += p3.x; a1.w += p3.y;
        }
    }

    const float4* b4 = reinterpret_cast<const float4*>(bias);
    float4 b0 = __ldg(b4 + 2 * lane);
    float4 b1 = __ldg(b4 + 2 * lane + 1);
    a0.x = fmaxf(a0.x + b0.x, 0.f); a0.y = fmaxf(a0.y + b0.y, 0.f);
    a0.z = fmaxf(a0.z + b0.z, 0.f); a0.w = fmaxf(a0.w + b0.w, 0.f);
    a1.x = fmaxf(a1.x + b1.x, 0.f); a1.y = fmaxf(a1.y + b1.y, 0.f);
    a1.z = fmaxf(a1.z + b1.z, 0.f); a1.w = fmaxf(a1.w + b1.w, 0.f);
    h4[2 * lane]     = a0;
    h4[2 * lane + 1] = a1;
}

// ---------------------------------------------------------------------------
// Launch DAG:
//   side:  conv_w -> (e_w) -> zero_cnt -> bucket_fill -> (e_join)
//   main:  conv_x -> wait(e_w) -> gemm -> wait(e_join) -> gather_finalize
// ---------------------------------------------------------------------------
extern "C" void kernel_launch(void* const* d_in, const int* in_sizes, int n_in,
                              void* d_out, int out_size)
{
    const float* x    = (const float*)d_in[0];
    const float* Ws   = (const float*)d_in[1];
    const float* W1   = (const float*)d_in[2];
    const float* W2   = (const float*)d_in[3];
    const float* bias = (const float*)d_in[4];
    const int* src1   = (const int*)d_in[5];
    const int* dst1   = (const int*)d_in[6];
    const int* src2   = (const int*)d_in[7];
    const int* dst2   = (const int*)d_in[8];
    float* h = (float*)d_out;

    cudaFuncSetAttribute(gemm_mma, cudaFuncAttributeMaxDynamicSharedMemorySize, GEMM_SMEM);

    cudaStream_t s2;
    cudaEvent_t e_fork, e_w, e_join;
    cudaStreamCreateWithFlags(&s2, cudaStreamNonBlocking);
    cudaEventCreateWithFlags(&e_fork, cudaEventDisableTiming);
    cudaEventCreateWithFlags(&e_w,    cudaEventDisableTiming);
    cudaEventCreateWithFlags(&e_join, cudaEventDisableTiming);

    // fork
    cudaEventRecord(e_fork, 0);
    cudaStreamWaitEvent(s2, e_fork, 0);

    // side stream: W conversion, then buckets
    conv_w<<<(3 * DIM * DIM + 255) / 256, 256, 0, s2>>>(Ws, W1, W2);
    cudaEventRecord(e_w, s2);
    zero_cnt<<<(2 * NN + 255) / 256, 256, 0, s2>>>();
    dim3 fgrid((NE + 255) / 256, 2);
    bucket_fill<<<fgrid, 256, 0, s2>>>(src1, dst1, src2, dst2, h);
    cudaEventRecord(e_join, s2);

    // main stream: x conversion, gemm (after W ready)
    int nx = (int)(((size_t)NN * DIM / 4 + 255) / 256);
    conv_x<<<nx, 256>>>(x);
    cudaStreamWaitEvent(0, e_w, 0);
    dim3 ggrid(6, MTILES);
    gemm_mma<<<ggrid, 256, GEMM_SMEM>>>(h);

    // join, then finalize
    cudaStreamWaitEvent(0, e_join, 0);
    gather_finalize<<<(NN * 32 + 255) / 256, 256>>>(h, bias);
}